// round 12
// baseline (speedup 1.0000x reference)
#include <cuda_runtime.h>

// Hopf oscillator scan — FINAL (converged R10, replay-verified R11).
// Scalar layout (1 channel/thread, 262144 threads), PF=4 register ring,
// fully-unrolled t-loop (T=64), streaming .cs reads, default-policy stores,
// __launch_bounds__(256, 7) pinning regs to 30.
//
// Convergence evidence (R1-R11): five structurally distinct kernels
// (float4/float2/scalar widths, clamped/split/fully-unrolled loops,
// .cs vs default store policy) all land at 38.7-39.2us kernel time
// = 6.6 TB/s on 256MB compulsory traffic (~83% of 8TB/s HBM3e spec),
// at the B300 LTS/DRAM mixed read-write ceiling. Occupancy grid-limited
// (79%, single wave), all compute pipes <=12%, traffic irreducible
// (nonlinear scan: r^3 and sin(phi) feedback forbid reassociation).
// R11 replay reproduced dur to the microsecond — plateau verified.

#define HOPF_DT      0.01f
#define HOPF_SCALER  20.0f

static constexpr int BS  = 8;
static constexpr int T   = 64;
static constexpr int CPB = 32 * 32 * 32;   // channels per batch = 32768
static constexpr int PF  = 4;              // prefetch ring depth (power of 2)

__global__ __launch_bounds__(256, 7)
void hopf_scan_kernel(const float* __restrict__ Xr,
                      const float* __restrict__ Xi,
                      const float* __restrict__ Om,
                      float* __restrict__ OutR,
                      float* __restrict__ OutI)
{
    const int u = blockIdx.x * blockDim.x + threadIdx.x;  // 0..262143
    const int b = u >> 15;            // / CPB
    const int c = u & (CPB - 1);      // % CPB

    const float om = Om[c];

    float r = 1.0f, phi = 0.0f, cs = 1.0f, sn = 0.0f;

    const int base = (b * T) * CPB + c;

    // Preload stages t = 0..PF-2 (streaming reads: no L2 pollution)
    float xrb[PF], xib[PF];
#pragma unroll
    for (int p = 0; p < PF - 1; ++p) {
        xrb[p] = __ldcs(Xr + base + p * CPB);
        xib[p] = __ldcs(Xi + base + p * CPB);
    }

    // Fully unrolled: t is a compile-time constant per iteration — the tail
    // predicate folds away, ring slots become registers, offsets become
    // immediates, and ptxas batches loads ahead of the compute chain.
#pragma unroll
    for (int t = 0; t < T; ++t) {
        if (t + PF - 1 < T) {   // compile-time predicate
            const int tp = t + PF - 1;
            xrb[tp & (PF - 1)] = __ldcs(Xr + base + tp * CPB);
            xib[tp & (PF - 1)] = __ldcs(Xi + base + tp * CPB);
        }

        const float xr = xrb[t & (PF - 1)];
        const float xi = xib[t & (PF - 1)];

        const float input_r   = HOPF_SCALER * xr * cs;
        const float input_phi = HOPF_SCALER * xi * sn;
        r   = r + ((1.0f - r * r) * r + input_r) * HOPF_DT;
        phi = phi + (om - input_phi) * HOPF_DT;
        __sincosf(phi, &sn, &cs);

        const int off = base + t * CPB;
        OutR[off] = r * cs;   // default policy: L2 buffers the write stream
        OutI[off] = r * sn;
    }
}

extern "C" void kernel_launch(void* const* d_in, const int* in_sizes, int n_in,
                              void* d_out, int out_size)
{
    const float* Xr = (const float*)d_in[0];
    const float* Xi = (const float*)d_in[1];
    const float* Om = (const float*)d_in[2];

    float* out  = (float*)d_out;
    const int n_elem = BS * T * CPB;            // 16,777,216 per output tensor
    float* OutR = out;
    float* OutI = out + n_elem;

    const int n_threads = BS * CPB;             // 262144
    hopf_scan_kernel<<<n_threads / 256, 256>>>(Xr, Xi, Om, OutR, OutI);
}

// round 13
// speedup vs baseline: 1.0336x; 1.0336x over previous
#include <cuda_runtime.h>

// Hopf oscillator scan — FINAL (R10; replay-verified R11/R12).
// Scalar layout (1 channel/thread, 262144 threads), PF=4 register ring,
// fully-unrolled t-loop (T=64), streaming .cs reads, default-policy stores,
// __launch_bounds__(256, 7), 30 regs, occ ~79% (grid-limited, single wave).
//
// Session conclusion: kernel is at the B300 HBM3e mixed read/write ceiling —
// 256MB compulsory traffic at 6.6 TB/s (~83% of spec). Levers closed by
// experiment: MLP depth (R2/R5), occupancy (R3/R4), ALU elimination (R8),
// scheduler freedom (R9), store policy (R10), loop structure (R6/R7).
// Replays R11/R12 bound run noise at +-0.8us kernel / +-1.6us dur; this
// binary holds the session-best kernel time (38.7us) and dur (47.6us).

#define HOPF_DT      0.01f
#define HOPF_SCALER  20.0f

static constexpr int BS  = 8;
static constexpr int T   = 64;
static constexpr int CPB = 32 * 32 * 32;   // channels per batch = 32768
static constexpr int PF  = 4;              // prefetch ring depth (power of 2)

__global__ __launch_bounds__(256, 7)
void hopf_scan_kernel(const float* __restrict__ Xr,
                      const float* __restrict__ Xi,
                      const float* __restrict__ Om,
                      float* __restrict__ OutR,
                      float* __restrict__ OutI)
{
    const int u = blockIdx.x * blockDim.x + threadIdx.x;  // 0..262143
    const int b = u >> 15;            // / CPB
    const int c = u & (CPB - 1);      // % CPB

    const float om = Om[c];

    float r = 1.0f, phi = 0.0f, cs = 1.0f, sn = 0.0f;

    const int base = (b * T) * CPB + c;

    // Preload stages t = 0..PF-2 (streaming reads: no L2 pollution, which
    // preserves L2 capacity for buffering the write stream)
    float xrb[PF], xib[PF];
#pragma unroll
    for (int p = 0; p < PF - 1; ++p) {
        xrb[p] = __ldcs(Xr + base + p * CPB);
        xib[p] = __ldcs(Xi + base + p * CPB);
    }

    // Fully unrolled: t is a compile-time constant per iteration — the tail
    // predicate folds away, ring slots become registers, offsets become
    // immediates, and ptxas batches loads ahead of the compute chain.
#pragma unroll
    for (int t = 0; t < T; ++t) {
        if (t + PF - 1 < T) {   // compile-time predicate
            const int tp = t + PF - 1;
            xrb[tp & (PF - 1)] = __ldcs(Xr + base + tp * CPB);
            xib[tp & (PF - 1)] = __ldcs(Xi + base + tp * CPB);
        }

        const float xr = xrb[t & (PF - 1)];
        const float xi = xib[t & (PF - 1)];

        const float input_r   = HOPF_SCALER * xr * cs;
        const float input_phi = HOPF_SCALER * xi * sn;
        r   = r + ((1.0f - r * r) * r + input_r) * HOPF_DT;
        phi = phi + (om - input_phi) * HOPF_DT;
        __sincosf(phi, &sn, &cs);

        const int off = base + t * CPB;
        OutR[off] = r * cs;   // default policy: L2 buffers the write stream
        OutI[off] = r * sn;
    }
}

extern "C" void kernel_launch(void* const* d_in, const int* in_sizes, int n_in,
                              void* d_out, int out_size)
{
    const float* Xr = (const float*)d_in[0];
    const float* Xi = (const float*)d_in[1];
    const float* Om = (const float*)d_in[2];

    float* out  = (float*)d_out;
    const int n_elem = BS * T * CPB;            // 16,777,216 per output tensor
    float* OutR = out;
    float* OutI = out + n_elem;

    const int n_threads = BS * CPB;             // 262144
    hopf_scan_kernel<<<n_threads / 256, 256>>>(Xr, Xi, Om, OutR, OutI);
}